// round 13
// baseline (speedup 1.0000x reference)
#include <cuda_runtime.h>
#include <cuda_fp16.h>
#include <stdint.h>
#include <math.h>

#define NN 10000
#define EE 320000
#define UU 256

typedef __half fp16;

// ---------------- static device scratch ----------------
__device__ fp16  g_ehA[EE * UU];
__device__ fp16  g_elA[EE * UU];
__device__ fp16  g_ehB[EE * UU];
__device__ fp16  g_elB[EE * UU];
__device__ float g_xA[NN * UU];
__device__ float g_xB[NN * UU];
__device__ fp16  g_xh[NN * UU];
__device__ fp16  g_xl[NN * UU];
__device__ fp16  g_xcat[NN * 1024];    // fp16 node-GEMM outputs [xW1|xW2|xWs|xWt]
__device__ float g_agg[NN * UU];
__device__ fp16  g_Bw[19 * UU * UU];   // transposed [N,K] single-fp16 weight slots
__device__ float g_bcat[3 * 1024];
__device__ float g_prec[3584];         // layer-0 rank-collapse precomputes

// ---------------- helpers ----------------
__device__ __forceinline__ uint32_t smem_u32(const void* p) {
    uint32_t a;
    asm("{ .reg .u64 t; cvta.to.shared.u64 t, %1; cvt.u32.u64 %0, t; }" : "=r"(a) : "l"(p));
    return a;
}
__device__ __forceinline__ void ldsm4(uint32_t addr, uint32_t* r) {
    asm volatile("ldmatrix.sync.aligned.m8n8.x4.shared.b16 {%0,%1,%2,%3}, [%4];"
                 : "=r"(r[0]), "=r"(r[1]), "=r"(r[2]), "=r"(r[3]) : "r"(addr));
}
__device__ __forceinline__ void mma16816(float* c, const uint32_t* a, const uint32_t* b) {
    asm volatile(
        "mma.sync.aligned.m16n8k16.row.col.f32.f16.f16.f32 "
        "{%0,%1,%2,%3}, {%4,%5,%6,%7}, {%8,%9}, {%0,%1,%2,%3};"
        : "+f"(c[0]), "+f"(c[1]), "+f"(c[2]), "+f"(c[3])
        : "r"(a[0]), "r"(a[1]), "r"(a[2]), "r"(a[3]), "r"(b[0]), "r"(b[1]));
}
__device__ __forceinline__ void red_v4(float* addr, float a, float b, float c, float d) {
    asm volatile("red.global.add.v4.f32 [%0], {%1, %2, %3, %4};"
                 :: "l"(addr), "f"(a), "f"(b), "f"(c), "f"(d) : "memory");
}
__device__ __forceinline__ void split2(float v, fp16& h, fp16& l) {
    h = __float2half_rn(v);
    l = __float2half_rn(v - __half2float(h));
}
__device__ __forceinline__ float2 unpack2(uint32_t w) {
    __half2 h = *reinterpret_cast<__half2*>(&w);
    return __half22float2(h);
}
__device__ __forceinline__ uint32_t pack2(fp16 a, fp16 b) {
    __half2 h = __halves2half2(a, b);
    return *reinterpret_cast<uint32_t*>(&h);
}
__device__ __forceinline__ uint2 pack4f(float a, float b, float c, float d) {
    return make_uint2(pack2(__float2half_rn(a), __float2half_rn(b)),
                      pack2(__float2half_rn(c), __float2half_rn(d)));
}

// ---------------- prep kernels ----------------

__global__ void zero_kernel(float4* __restrict__ p, int n4) {
    int i = blockIdx.x * blockDim.x + threadIdx.x;
    if (i < n4) p[i] = make_float4(0.f, 0.f, 0.f, 0.f);
}

__global__ void convert_all_kernel(const float* __restrict__ W1, const float* __restrict__ W2,
                                   const float* __restrict__ Ws, const float* __restrict__ Wt,
                                   const float* __restrict__ We, const float* __restrict__ Wm1,
                                   const float* __restrict__ b1, const float* __restrict__ b2,
                                   fp16* __restrict__ Bw, float* __restrict__ bcat) {
    int i = blockIdx.x * blockDim.x + threadIdx.x;
    const int SQ = 18 * 65536;
    if (i < SQ) {
        int s = i >> 16, w = i & 65535;
        int k = w >> 8, n = w & 255;
        const float* srcp;
        if (s < 15) {
            int l = s / 5, t = s - l * 5;
            const float* bases[5] = {W1, W2, Ws, Wt, We};
            srcp = bases[t] + l * 65536;
        } else if (s == 15) srcp = Ws + 3 * 65536;
        else if (s == 16) srcp = Wt + 3 * 65536;
        else srcp = We + 3 * 65536;
        Bw[s * 65536 + n * 256 + k] = __float2half_rn(srcp[k * 256 + n]);
    } else if (i < SQ + 32768) {
        int w = i - SQ;
        int k = w >> 7, n = w & 127;
        Bw[18 * 65536 + n * 256 + k] = __float2half_rn(Wm1[k * 128 + n]);
    } else if (i < SQ + 32768 + 3072) {
        int w = i - SQ - 32768;
        int l = w >> 10, j = w & 1023;
        float v = 0.f;
        if (j < 256) v = b1[l * 256 + j];
        else if (j < 512) v = b2[l * 256 + (j - 256)];
        bcat[w] = v;
    }
}

// rank-collapse precomputes for layer 0
__global__ void precompute_kernel(const float* __restrict__ Wa, const float* __restrict__ ba,
                                  const float* __restrict__ We, const float* __restrict__ Wp,
                                  const float* __restrict__ bp,
                                  const float* __restrict__ W1, const float* __restrict__ W2,
                                  const float* __restrict__ Ws, const float* __restrict__ Wt,
                                  const float* __restrict__ b1, const float* __restrict__ b2,
                                  float* __restrict__ prec) {
    int n = blockIdx.x * blockDim.x + threadIdx.x;
    if (n >= 3584) return;
    if (n < 2048) {
        int p = n >> 10, col = n & 1023;
        const float* W = (col < 256) ? W1 : (col < 512) ? W2 : (col < 768) ? Ws : Wt;
        int nn = col & 255;
        float s = 0.f;
        for (int k = 0; k < 256; k++) s += Wp[p * 256 + k] * W[k * 256 + nn];
        prec[p * 1024 + col] = s;
    } else if (n < 3072) {
        int col = n - 2048;
        const float* W = (col < 256) ? W1 : (col < 512) ? W2 : (col < 768) ? Ws : Wt;
        int nn = col & 255;
        float s = 0.f;
        for (int k = 0; k < 256; k++) s += bp[k] * W[k * 256 + nn];
        if (col < 256) s += b1[col];
        else if (col < 512) s += b2[col - 256];
        prec[2048 + col] = s;
    } else if (n < 3328) {
        int nn = n - 3072;
        float s = 0.f;
        for (int k = 0; k < 256; k++) s += Wa[k] * We[k * 256 + nn];
        prec[3072 + nn] = s;
    } else {
        int nn = n - 3328;
        float s = 0.f;
        for (int k = 0; k < 256; k++) s += ba[k] * We[k * 256 + nn];
        prec[3328 + nn] = s;
    }
}

__global__ void init_x_kernel(const float* __restrict__ pos, const float* __restrict__ Wp,
                              const float* __restrict__ bp, float* __restrict__ x) {
    int i = blockIdx.x * blockDim.x + threadIdx.x;
    if (i >= NN * 64) return;
    int n = i >> 6, c = i & 63;
    float p0 = pos[n * 2 + 0], p1 = pos[n * 2 + 1];
    float4 w0 = ((const float4*)Wp)[c];
    float4 w1 = ((const float4*)Wp)[64 + c];
    float4 b = ((const float4*)bp)[c];
    float4 r;
    r.x = p0 * w0.x + p1 * w1.x + b.x;
    r.y = p0 * w0.y + p1 * w1.y + b.y;
    r.z = p0 * w0.z + p1 * w1.z + b.z;
    r.w = p0 * w0.w + p1 * w1.w + b.w;
    ((float4*)x)[i] = r;
}

// xcat0 = fp16(pos @ (Wp@Wcat0) + (bp@Wcat0 + bcat0))    [rank-2, no GEMM]
__global__ void layer0_node_kernel(const float* __restrict__ pos, const float* __restrict__ prec,
                                   fp16* __restrict__ xcat) {
    int i = blockIdx.x * blockDim.x + threadIdx.x;
    if (i >= NN * 256) return;
    int n = i >> 8, c = i & 255;
    float p0 = pos[n * 2 + 0], p1 = pos[n * 2 + 1];
    float4 w0 = ((const float4*)prec)[c];
    float4 w1 = ((const float4*)(prec + 1024))[c];
    float4 b = ((const float4*)(prec + 2048))[c];
    ((uint2*)xcat)[i] = pack4f(p0 * w0.x + p1 * w1.x + b.x,
                               p0 * w0.y + p1 * w1.y + b.y,
                               p0 * w0.z + p1 * w1.z + b.z,
                               p0 * w0.w + p1 * w1.w + b.w);
}

// layer-0 fused edge update + gated scatter  [rank-1 e0, no GEMM]
__global__ void layer0_edge_kernel(const float* __restrict__ ea, const int* __restrict__ src,
                                   const int* __restrict__ dst,
                                   const float* __restrict__ Wa, const float* __restrict__ ba,
                                   const float* __restrict__ be0, const float* __restrict__ prec,
                                   const fp16* __restrict__ xcat,
                                   fp16* __restrict__ Ch, fp16* __restrict__ Cl,
                                   float* __restrict__ agg) {
    int i = blockIdx.x * blockDim.x + threadIdx.x;
    if (i >= EE * 64) return;
    int m = i >> 6, c = i & 63;
    float a = ea[m];
    int s = src[m], d = dst[m];
    float4 wa = ((const float4*)Wa)[c];
    float4 bav = ((const float4*)ba)[c];
    float4 vv = ((const float4*)(prec + 3072))[c];
    float4 cc = ((const float4*)(prec + 3328))[c];
    float4 bev = ((const float4*)be0)[c];
    uint2 gsw = ((const uint2*)(xcat + (size_t)s * 1024 + 512))[c];
    uint2 gtw = ((const uint2*)(xcat + (size_t)d * 1024 + 768))[c];
    uint2 w2w = ((const uint2*)(xcat + (size_t)s * 1024 + 256))[c];
    float2 gs01 = unpack2(gsw.x), gs23 = unpack2(gsw.y);
    float2 gt01 = unpack2(gtw.x), gt23 = unpack2(gtw.y);
    float2 w201 = unpack2(w2w.x), w223 = unpack2(w2w.y);

    float e0 = a * wa.x + bav.x, e1 = a * wa.y + bav.y;
    float e2 = a * wa.z + bav.z, e3 = a * wa.w + bav.w;
    float v0 = e0 + fmaxf(a * vv.x + cc.x + gs01.x + gt01.x + bev.x, 0.f);
    float v1 = e1 + fmaxf(a * vv.y + cc.y + gs01.y + gt01.y + bev.y, 0.f);
    float v2 = e2 + fmaxf(a * vv.z + cc.z + gs23.x + gt23.x + bev.z, 0.f);
    float v3 = e3 + fmaxf(a * vv.w + cc.w + gs23.y + gt23.y + bev.w, 0.f);
    fp16 h0, l0, h1, l1, h2, l2, h3, l3;
    split2(v0, h0, l0); split2(v1, h1, l1); split2(v2, h2, l2); split2(v3, h3, l3);
    ((uint2*)Ch)[i] = make_uint2(pack2(h0, h1), pack2(h2, h3));
    ((uint2*)Cl)[i] = make_uint2(pack2(l0, l1), pack2(l2, l3));
    red_v4(agg + (size_t)d * 256 + c * 4,
           w201.x / (1.f + __expf(-e0)), w201.y / (1.f + __expf(-e1)),
           w223.x / (1.f + __expf(-e2)), w223.y / (1.f + __expf(-e3)));
}

__global__ void node_update_kernel(const float* __restrict__ x, const fp16* __restrict__ xcat,
                                   const float* __restrict__ agg, float* __restrict__ xo,
                                   fp16* __restrict__ xh, fp16* __restrict__ xl) {
    int i = blockIdx.x * blockDim.x + threadIdx.x;
    if (i >= NN * 64) return;
    int n = i >> 6, c = i & 63;
    float4 xv = ((const float4*)x)[i];
    uint2 wvw = ((const uint2*)(xcat + (size_t)n * 1024))[c];
    float2 wv01 = unpack2(wvw.x), wv23 = unpack2(wvw.y);
    float4 av = ((const float4*)agg)[i];
    float4 r;
    r.x = xv.x + fmaxf(wv01.x + av.x, 0.f);
    r.y = xv.y + fmaxf(wv01.y + av.y, 0.f);
    r.z = xv.z + fmaxf(wv23.x + av.z, 0.f);
    r.w = xv.w + fmaxf(wv23.y + av.w, 0.f);
    ((float4*)xo)[i] = r;
    fp16 h0, l0, h1, l1, h2, l2, h3, l3;
    split2(r.x, h0, l0); split2(r.y, h1, l1); split2(r.z, h2, l2); split2(r.w, h3, l3);
    ((uint2*)xh)[i] = make_uint2(pack2(h0, h1), pack2(h2, h3));
    ((uint2*)xl)[i] = make_uint2(pack2(l0, l1), pack2(l2, l3));
}

// ---------------- pipelined mma.sync split-fp16 GEMM ----------------
// 256 threads (8 warps, 2x4), CTA tile 128x128, warp tile 64x32.
// K=256 in 4 chunks of 64, cp.async double-buffered, 2 CTAs/SM (96KB each).
// mode 0: Cst[m*ldC+n] = fp16(D + bias)      (fp16 output into xcat)
// mode 1: edge residual + hi/lo re-split + gated scatter (fp16 gathers);
//         epilogue reconstructs e = Ah+Al regardless of `split`.
// mode 2: fused MLP head (fp32 out)

#define OFF_AH 0
#define OFF_AL 16384
#define OFF_B  32768
#define BUF_STRIDE 49152
#define CS_LD 132
#define SMEM_TOTAL 98304

__device__ __forceinline__ void stage_tile(uint32_t sdst, const fp16* __restrict__ G,
                                           int r0, int rmax, int k0, int tid) {
#pragma unroll
    for (int t = 0; t < 4; t++) {
        int idx = tid + t * 256;
        int r = idx >> 3, c = idx & 7;
        int gr = r0 + r;
        const fp16* srcp = G + (size_t)gr * UU + k0 + c * 8;
        uint32_t dst = sdst + r * 128 + (((c ^ (r & 7))) << 4);
        int sz = (gr < rmax) ? 16 : 0;
        asm volatile("cp.async.cg.shared.global [%0], [%1], 16, %2;"
                     :: "r"(dst), "l"(srcp), "r"(sz));
    }
}

__global__ void __launch_bounds__(256, 2)
mma_gemm(const fp16* __restrict__ Ah, const fp16* __restrict__ Al,
         const fp16* __restrict__ Bw,
         int M, int mode, int split,
         const float* __restrict__ bias, float* __restrict__ C,
         fp16* __restrict__ Cst, int ldC,
         const int* __restrict__ src, const int* __restrict__ dst,
         const fp16* __restrict__ gS, const fp16* __restrict__ gT, int gLd,
         const float* __restrict__ beL,
         fp16* __restrict__ Ch, fp16* __restrict__ Cl,
         const fp16* __restrict__ gW2, float* __restrict__ agg,
         const float* __restrict__ ea, const float* __restrict__ bm1,
         const float* __restrict__ alpha, const float* __restrict__ Wm1r,
         const float* __restrict__ Wm2, const float* __restrict__ bm2) {
    extern __shared__ __align__(1024) uint8_t smem_raw[];
    uint32_t sbase = smem_u32(smem_raw);
    int tid = threadIdx.x;
    int lane = tid & 31;
    int wid = tid >> 5;
    int wm = wid >> 2;
    int wn = wid & 3;
    int col0 = blockIdx.x * 128;
    int row0 = blockIdx.y * 128;

    float acc[4][4][4];
#pragma unroll
    for (int a = 0; a < 4; a++)
#pragma unroll
        for (int b = 0; b < 4; b++)
#pragma unroll
            for (int c = 0; c < 4; c++) acc[a][b][c] = 0.f;

    int arow = lane & 15;
    int achunk = lane >> 4;
    int brow = (lane & 7) + ((lane >> 4) << 3);
    int bchunk = (lane >> 3) & 1;

    stage_tile(sbase + OFF_AH, Ah, row0, M, 0, tid);
    if (split) stage_tile(sbase + OFF_AL, Al, row0, M, 0, tid);
    stage_tile(sbase + OFF_B, Bw, col0, 1 << 30, 0, tid);
    asm volatile("cp.async.commit_group;");

    for (int kc = 0; kc < 4; kc++) {
        if (kc < 3) {
            uint32_t nb = sbase + ((kc + 1) & 1) * BUF_STRIDE;
            int k0 = (kc + 1) * 64;
            stage_tile(nb + OFF_AH, Ah, row0, M, k0, tid);
            if (split) stage_tile(nb + OFF_AL, Al, row0, M, k0, tid);
            stage_tile(nb + OFF_B, Bw, col0, 1 << 30, k0, tid);
            asm volatile("cp.async.commit_group;");
            asm volatile("cp.async.wait_group 1;");
        } else {
            asm volatile("cp.async.wait_group 0;");
        }
        __syncthreads();

        uint32_t base = sbase + (kc & 1) * BUF_STRIDE;
#pragma unroll
        for (int kk = 0; kk < 4; kk++) {
            uint32_t bf[2][4];
#pragma unroll
            for (int nt2 = 0; nt2 < 2; nt2++) {
                int r = wn * 32 + nt2 * 16 + brow;
                int ch = kk * 2 + bchunk;
                uint32_t off = (uint32_t)(r * 128 + (((ch ^ (r & 7))) << 4));
                ldsm4(base + OFF_B + off, bf[nt2]);
            }
#pragma unroll
            for (int mt = 0; mt < 4; mt++) {
                int r = wm * 64 + mt * 16 + arow;
                int ch = kk * 2 + achunk;
                uint32_t off = (uint32_t)(r * 128 + (((ch ^ (r & 7))) << 4));
                uint32_t ah[4];
                ldsm4(base + OFF_AH + off, ah);
#pragma unroll
                for (int nt = 0; nt < 4; nt++)
                    mma16816(acc[mt][nt], ah, &bf[nt >> 1][(nt & 1) * 2]);
                if (split) {
                    uint32_t al[4];
                    ldsm4(base + OFF_AL + off, al);
#pragma unroll
                    for (int nt = 0; nt < 4; nt++)
                        mma16816(acc[mt][nt], al, &bf[nt >> 1][(nt & 1) * 2]);
                }
            }
        }
        __syncthreads();
    }

    float* Cs = (float*)smem_raw;
#pragma unroll
    for (int mt = 0; mt < 4; mt++) {
#pragma unroll
        for (int nt = 0; nt < 4; nt++) {
            int r = wm * 64 + mt * 16 + (lane >> 2);
            int cl = wn * 32 + nt * 8 + (lane & 3) * 2;
            Cs[r * CS_LD + cl] = acc[mt][nt][0];
            Cs[r * CS_LD + cl + 1] = acc[mt][nt][1];
            Cs[(r + 8) * CS_LD + cl] = acc[mt][nt][2];
            Cs[(r + 8) * CS_LD + cl + 1] = acc[mt][nt][3];
        }
    }
    __syncthreads();

    int nl = lane * 4;
#pragma unroll 1
    for (int it = 0; it < 16; it++) {
        int r = wid * 16 + it;
        int m = row0 + r;
        if (m >= M) continue;
        const float* crow = Cs + r * CS_LD;
        int n = col0 + nl;
        if (mode == 0) {
            float4 v = *(const float4*)&crow[nl];
            if (bias) {
                float4 b4 = *(const float4*)&bias[n];
                v.x += b4.x; v.y += b4.y; v.z += b4.z; v.w += b4.w;
            }
            *(uint2*)&Cst[(size_t)m * ldC + n] = pack4f(v.x, v.y, v.z, v.w);
        } else if (mode == 1) {
            int sIdx = src[m], dIdx = dst[m];
            float4 d4 = *(const float4*)&crow[nl];
            uint2 hb = *(const uint2*)&Ah[(size_t)m * 256 + n];
            uint2 lb = *(const uint2*)&Al[(size_t)m * 256 + n];
            float2 h01 = unpack2(hb.x), h23 = unpack2(hb.y);
            float2 l01 = unpack2(lb.x), l23 = unpack2(lb.y);
            float e0 = h01.x + l01.x, e1 = h01.y + l01.y;
            float e2 = h23.x + l23.x, e3 = h23.y + l23.y;
            uint2 gsw = *(const uint2*)&gS[(size_t)sIdx * gLd + n];
            uint2 gtw = *(const uint2*)&gT[(size_t)dIdx * gLd + n];
            float2 gs01 = unpack2(gsw.x), gs23 = unpack2(gsw.y);
            float2 gt01 = unpack2(gtw.x), gt23 = unpack2(gtw.y);
            float4 be4 = *(const float4*)&beL[n];
            float v0 = e0 + fmaxf(d4.x + gs01.x + gt01.x + be4.x, 0.f);
            float v1 = e1 + fmaxf(d4.y + gs01.y + gt01.y + be4.y, 0.f);
            float v2 = e2 + fmaxf(d4.z + gs23.x + gt23.x + be4.z, 0.f);
            float v3 = e3 + fmaxf(d4.w + gs23.y + gt23.y + be4.w, 0.f);
            fp16 h0, l0, h1, l1, h2, l2, h3, l3;
            split2(v0, h0, l0); split2(v1, h1, l1);
            split2(v2, h2, l2); split2(v3, h3, l3);
            *(uint2*)&Ch[(size_t)m * 256 + n] = make_uint2(pack2(h0, h1), pack2(h2, h3));
            *(uint2*)&Cl[(size_t)m * 256 + n] = make_uint2(pack2(l0, l1), pack2(l2, l3));
            if (gW2) {
                uint2 w2w = *(const uint2*)&gW2[(size_t)sIdx * gLd + n];
                float2 w201 = unpack2(w2w.x), w223 = unpack2(w2w.y);
                red_v4(agg + (size_t)dIdx * 256 + n,
                       w201.x / (1.f + __expf(-e0)), w201.y / (1.f + __expf(-e1)),
                       w223.x / (1.f + __expf(-e2)), w223.y / (1.f + __expf(-e3)));
            }
        } else {
            float alpha0 = alpha[0];
            float eam = ea[m];
            float4 d4 = *(const float4*)&crow[nl];
            float4 wr = *(const float4*)&Wm1r[nl];
            float4 bb = *(const float4*)&bm1[nl];
            float4 w2 = *(const float4*)&Wm2[nl];
            float h0 = d4.x + eam * wr.x + bb.x;
            float h1 = d4.y + eam * wr.y + bb.y;
            float h2 = d4.z + eam * wr.z + bb.z;
            float h3 = d4.w + eam * wr.w + bb.w;
            h0 = (h0 > 0.f) ? h0 : alpha0 * h0;
            h1 = (h1 > 0.f) ? h1 : alpha0 * h1;
            h2 = (h2 > 0.f) ? h2 : alpha0 * h2;
            h3 = (h3 > 0.f) ? h3 : alpha0 * h3;
            float partial = h0 * w2.x + h1 * w2.y + h2 * w2.z + h3 * w2.w;
#pragma unroll
            for (int s = 16; s > 0; s >>= 1)
                partial += __shfl_xor_sync(0xffffffffu, partial, s);
            if (lane == 0) C[m] = partial + bm2[0];
        }
    }
}

// ---------------- host ----------------

static void mma_launch(const fp16* Ah, const fp16* Al, const fp16* Bw,
                       int M, int Nc, int mode, int split,
                       const float* bias, float* C, fp16* Cst, int ldC,
                       const int* src = nullptr, const int* dst = nullptr,
                       const fp16* gS = nullptr, const fp16* gT = nullptr, int gLd = 0,
                       const float* beL = nullptr,
                       fp16* Ch = nullptr, fp16* Cl = nullptr,
                       const fp16* gW2 = nullptr, float* agg = nullptr,
                       const float* ea = nullptr, const float* bm1 = nullptr,
                       const float* alpha = nullptr, const float* Wm1r = nullptr,
                       const float* Wm2 = nullptr, const float* bm2 = nullptr) {
    dim3 grid(Nc / 128, (M + 127) / 128);
    mma_gemm<<<grid, 256, SMEM_TOTAL>>>(Ah, Al, Bw, M, mode, split, bias, C, Cst, ldC,
                                        src, dst, gS, gT, gLd, beL, Ch, Cl,
                                        gW2, agg, ea, bm1, alpha, Wm1r, Wm2, bm2);
}

extern "C" void kernel_launch(void* const* d_in, const int* in_sizes, int n_in,
                              void* d_out, int out_size) {
    const float* pos   = (const float*)d_in[0];
    const float* ea    = (const float*)d_in[1];
    const int*   ei    = (const int*)d_in[2];
    const float* Wp    = (const float*)d_in[3];
    const float* bp    = (const float*)d_in[4];
    const float* Wa    = (const float*)d_in[5];
    const float* ba    = (const float*)d_in[6];
    const float* W1    = (const float*)d_in[7];
    const float* b1    = (const float*)d_in[8];
    const float* W2    = (const float*)d_in[9];
    const float* b2    = (const float*)d_in[10];
    const float* We    = (const float*)d_in[11];
    const float* be    = (const float*)d_in[12];
    const float* Ws    = (const float*)d_in[13];
    const float* Wt    = (const float*)d_in[14];
    const float* Wm1   = (const float*)d_in[15];
    const float* bm1   = (const float*)d_in[16];
    const float* alpha = (const float*)d_in[17];
    const float* Wm2   = (const float*)d_in[18];
    const float* bm2   = (const float*)d_in[19];
    float* out = (float*)d_out;

    const int* src = ei;
    const int* dst = ei + EE;

    cudaFuncSetAttribute(mma_gemm, cudaFuncAttributeMaxDynamicSharedMemorySize, SMEM_TOTAL);

    float *xA, *xB, *agg, *bcat, *prec;
    fp16 *ehA, *elA, *ehB, *elB, *xh, *xl, *xcat, *Bw;
    cudaGetSymbolAddress((void**)&ehA, g_ehA);
    cudaGetSymbolAddress((void**)&elA, g_elA);
    cudaGetSymbolAddress((void**)&ehB, g_ehB);
    cudaGetSymbolAddress((void**)&elB, g_elB);
    cudaGetSymbolAddress((void**)&xA, g_xA);
    cudaGetSymbolAddress((void**)&xB, g_xB);
    cudaGetSymbolAddress((void**)&xh, g_xh);
    cudaGetSymbolAddress((void**)&xl, g_xl);
    cudaGetSymbolAddress((void**)&xcat, g_xcat);
    cudaGetSymbolAddress((void**)&agg, g_agg);
    cudaGetSymbolAddress((void**)&Bw, g_Bw);
    cudaGetSymbolAddress((void**)&bcat, g_bcat);
    cudaGetSymbolAddress((void**)&prec, g_prec);

    const int TB = 256;
    const int SLOT = UU * UU;

    int convN = 18 * 65536 + 32768 + 3072;
    convert_all_kernel<<<(convN + TB - 1) / TB, TB>>>(W1, W2, Ws, Wt, We, Wm1,
                                                      b1, b2, Bw, bcat);
    precompute_kernel<<<(3584 + TB - 1) / TB, TB>>>(Wa, ba, We, Wp, bp,
                                                    W1, W2, Ws, Wt, b1, b2, prec);
    init_x_kernel<<<(NN * 64 + TB - 1) / TB, TB>>>(pos, Wp, bp, xA);

    // --- layer 0 (rank-collapsed; no GEMMs) ---
    zero_kernel<<<(NN * 64 + TB - 1) / TB, TB>>>((float4*)agg, NN * 64);
    layer0_node_kernel<<<(NN * 256 + TB - 1) / TB, TB>>>(pos, prec, xcat);
    layer0_edge_kernel<<<(EE * 64 + TB - 1) / TB, TB>>>(ea, src, dst, Wa, ba, be,
                                                        prec, xcat, ehA, elA, agg);
    node_update_kernel<<<(NN * 64 + TB - 1) / TB, TB>>>(xA, xcat, agg, xB, xh, xl);

    float* xc = xB; float* xn = xA;
    fp16 *ehc = ehA, *elc = elA, *ehn = ehB, *eln = elB;

    // --- layers 1, 2 (edge GEMMs hi-only; epilogue still exact e = hi+lo) ---
    for (int l = 1; l < 3; l++) {
        zero_kernel<<<(NN * 64 + TB - 1) / TB, TB>>>((float4*)agg, NN * 64);
        mma_launch(xh, xl, Bw + (l * 5) * SLOT,
                   NN, 1024, 0, 1, bcat + l * 1024, nullptr, xcat, 1024);
        mma_launch(ehc, elc, Bw + (l * 5 + 4) * SLOT,
                   EE, 256, 1, 0, nullptr, nullptr, nullptr, 0,
                   src, dst, xcat + 512, xcat + 768, 1024,
                   be + l * 256, ehn, eln,
                   xcat + 256, agg);
        node_update_kernel<<<(NN * 64 + TB - 1) / TB, TB>>>(xc, xcat, agg, xn, xh, xl);
        { float* t = xc; xc = xn; xn = t; }
        { fp16* t = ehc; ehc = ehn; ehn = t; }
        { fp16* t = elc; elc = eln; eln = t; }
    }

    // --- final edge update (l=3, hi-only) ---
    mma_launch(xh, xl, Bw + 15 * SLOT,
               NN, 512, 0, 1, nullptr, nullptr, xcat, 1024);
    mma_launch(ehc, elc, Bw + 17 * SLOT,
               EE, 256, 1, 0, nullptr, nullptr, nullptr, 0,
               src, dst, xcat, xcat + 256, 1024,
               be + 3 * 256, ehn, eln,
               nullptr, nullptr);
    { fp16* t = ehc; ehc = ehn; ehn = t; }
    { fp16* t = elc; elc = eln; eln = t; }

    // --- fused MLP head (single col tile, hi-only A, direct store) ---
    mma_launch(ehc, elc, Bw + 18 * SLOT,
               EE, 128, 2, 0, nullptr, out, nullptr, 0,
               nullptr, nullptr, nullptr, nullptr, 0, nullptr,
               nullptr, nullptr, nullptr, nullptr,
               ea, bm1, alpha, Wm1 + 256 * 128, Wm2, bm2);

    (void)in_sizes; (void)n_in; (void)out_size;
}

// round 15
// speedup vs baseline: 1.0962x; 1.0962x over previous
#include <cuda_runtime.h>
#include <cuda_fp16.h>
#include <stdint.h>
#include <math.h>

#define NN 10000
#define EE 320000
#define UU 256

typedef __half fp16;

// ---------------- static device scratch ----------------
__device__ fp16  g_ehA[EE * UU];
__device__ fp16  g_elA[EE * UU];
__device__ fp16  g_ehB[EE * UU];
__device__ fp16  g_elB[EE * UU];
__device__ float g_xA[NN * UU];
__device__ float g_xB[NN * UU];
__device__ fp16  g_xh[NN * UU];
__device__ fp16  g_xl[NN * UU];
__device__ fp16  g_xcat[NN * 1024];    // fp16 node-GEMM outputs [xW1|xW2|xWs|xWt]
__device__ float g_agg[NN * UU];
__device__ fp16  g_Bw[19 * UU * UU];   // transposed [N,K] single-fp16 weight slots
__device__ float g_bcat[3 * 1024];
__device__ float g_prec[3584];         // layer-0 rank-collapse precomputes

// ---------------- helpers ----------------
__device__ __forceinline__ uint32_t smem_u32(const void* p) {
    uint32_t a;
    asm("{ .reg .u64 t; cvta.to.shared.u64 t, %1; cvt.u32.u64 %0, t; }" : "=r"(a) : "l"(p));
    return a;
}
__device__ __forceinline__ void ldsm4(uint32_t addr, uint32_t* r) {
    asm volatile("ldmatrix.sync.aligned.m8n8.x4.shared.b16 {%0,%1,%2,%3}, [%4];"
                 : "=r"(r[0]), "=r"(r[1]), "=r"(r[2]), "=r"(r[3]) : "r"(addr));
}
__device__ __forceinline__ void mma16816(float* c, const uint32_t* a, const uint32_t* b) {
    asm volatile(
        "mma.sync.aligned.m16n8k16.row.col.f32.f16.f16.f32 "
        "{%0,%1,%2,%3}, {%4,%5,%6,%7}, {%8,%9}, {%0,%1,%2,%3};"
        : "+f"(c[0]), "+f"(c[1]), "+f"(c[2]), "+f"(c[3])
        : "r"(a[0]), "r"(a[1]), "r"(a[2]), "r"(a[3]), "r"(b[0]), "r"(b[1]));
}
__device__ __forceinline__ void red_v4(float* addr, float a, float b, float c, float d) {
    asm volatile("red.global.add.v4.f32 [%0], {%1, %2, %3, %4};"
                 :: "l"(addr), "f"(a), "f"(b), "f"(c), "f"(d) : "memory");
}
__device__ __forceinline__ void split2(float v, fp16& h, fp16& l) {
    h = __float2half_rn(v);
    l = __float2half_rn(v - __half2float(h));
}
__device__ __forceinline__ float2 unpack2(uint32_t w) {
    __half2 h = *reinterpret_cast<__half2*>(&w);
    return __half22float2(h);
}
__device__ __forceinline__ uint32_t pack2(fp16 a, fp16 b) {
    __half2 h = __halves2half2(a, b);
    return *reinterpret_cast<uint32_t*>(&h);
}
__device__ __forceinline__ uint2 pack4f(float a, float b, float c, float d) {
    return make_uint2(pack2(__float2half_rn(a), __float2half_rn(b)),
                      pack2(__float2half_rn(c), __float2half_rn(d)));
}

// ---------------- prep kernels ----------------

__global__ void zero_kernel(float4* __restrict__ p, int n4) {
    int i = blockIdx.x * blockDim.x + threadIdx.x;
    if (i < n4) p[i] = make_float4(0.f, 0.f, 0.f, 0.f);
}

__global__ void convert_all_kernel(const float* __restrict__ W1, const float* __restrict__ W2,
                                   const float* __restrict__ Ws, const float* __restrict__ Wt,
                                   const float* __restrict__ We, const float* __restrict__ Wm1,
                                   const float* __restrict__ b1, const float* __restrict__ b2,
                                   fp16* __restrict__ Bw, float* __restrict__ bcat) {
    int i = blockIdx.x * blockDim.x + threadIdx.x;
    const int SQ = 18 * 65536;
    if (i < SQ) {
        int s = i >> 16, w = i & 65535;
        int k = w >> 8, n = w & 255;
        const float* srcp;
        if (s < 15) {
            int l = s / 5, t = s - l * 5;
            const float* bases[5] = {W1, W2, Ws, Wt, We};
            srcp = bases[t] + l * 65536;
        } else if (s == 15) srcp = Ws + 3 * 65536;
        else if (s == 16) srcp = Wt + 3 * 65536;
        else srcp = We + 3 * 65536;
        Bw[s * 65536 + n * 256 + k] = __float2half_rn(srcp[k * 256 + n]);
    } else if (i < SQ + 32768) {
        int w = i - SQ;
        int k = w >> 7, n = w & 127;
        Bw[18 * 65536 + n * 256 + k] = __float2half_rn(Wm1[k * 128 + n]);
    } else if (i < SQ + 32768 + 3072) {
        int w = i - SQ - 32768;
        int l = w >> 10, j = w & 1023;
        float v = 0.f;
        if (j < 256) v = b1[l * 256 + j];
        else if (j < 512) v = b2[l * 256 + (j - 256)];
        bcat[w] = v;
    }
}

// rank-collapse precomputes for layer 0
__global__ void precompute_kernel(const float* __restrict__ Wa, const float* __restrict__ ba,
                                  const float* __restrict__ We, const float* __restrict__ Wp,
                                  const float* __restrict__ bp,
                                  const float* __restrict__ W1, const float* __restrict__ W2,
                                  const float* __restrict__ Ws, const float* __restrict__ Wt,
                                  const float* __restrict__ b1, const float* __restrict__ b2,
                                  float* __restrict__ prec) {
    int n = blockIdx.x * blockDim.x + threadIdx.x;
    if (n >= 3584) return;
    if (n < 2048) {
        int p = n >> 10, col = n & 1023;
        const float* W = (col < 256) ? W1 : (col < 512) ? W2 : (col < 768) ? Ws : Wt;
        int nn = col & 255;
        float s = 0.f;
        for (int k = 0; k < 256; k++) s += Wp[p * 256 + k] * W[k * 256 + nn];
        prec[p * 1024 + col] = s;
    } else if (n < 3072) {
        int col = n - 2048;
        const float* W = (col < 256) ? W1 : (col < 512) ? W2 : (col < 768) ? Ws : Wt;
        int nn = col & 255;
        float s = 0.f;
        for (int k = 0; k < 256; k++) s += bp[k] * W[k * 256 + nn];
        if (col < 256) s += b1[col];
        else if (col < 512) s += b2[col - 256];
        prec[2048 + col] = s;
    } else if (n < 3328) {
        int nn = n - 3072;
        float s = 0.f;
        for (int k = 0; k < 256; k++) s += Wa[k] * We[k * 256 + nn];
        prec[3072 + nn] = s;
    } else {
        int nn = n - 3328;
        float s = 0.f;
        for (int k = 0; k < 256; k++) s += ba[k] * We[k * 256 + nn];
        prec[3328 + nn] = s;
    }
}

__global__ void init_x_kernel(const float* __restrict__ pos, const float* __restrict__ Wp,
                              const float* __restrict__ bp, float* __restrict__ x) {
    int i = blockIdx.x * blockDim.x + threadIdx.x;
    if (i >= NN * 64) return;
    int n = i >> 6, c = i & 63;
    float p0 = pos[n * 2 + 0], p1 = pos[n * 2 + 1];
    float4 w0 = ((const float4*)Wp)[c];
    float4 w1 = ((const float4*)Wp)[64 + c];
    float4 b = ((const float4*)bp)[c];
    float4 r;
    r.x = p0 * w0.x + p1 * w1.x + b.x;
    r.y = p0 * w0.y + p1 * w1.y + b.y;
    r.z = p0 * w0.z + p1 * w1.z + b.z;
    r.w = p0 * w0.w + p1 * w1.w + b.w;
    ((float4*)x)[i] = r;
}

// xcat0 = fp16(pos @ (Wp@Wcat0) + (bp@Wcat0 + bcat0))    [rank-2, no GEMM]
__global__ void layer0_node_kernel(const float* __restrict__ pos, const float* __restrict__ prec,
                                   fp16* __restrict__ xcat) {
    int i = blockIdx.x * blockDim.x + threadIdx.x;
    if (i >= NN * 256) return;
    int n = i >> 8, c = i & 255;
    float p0 = pos[n * 2 + 0], p1 = pos[n * 2 + 1];
    float4 w0 = ((const float4*)prec)[c];
    float4 w1 = ((const float4*)(prec + 1024))[c];
    float4 b = ((const float4*)(prec + 2048))[c];
    ((uint2*)xcat)[i] = pack4f(p0 * w0.x + p1 * w1.x + b.x,
                               p0 * w0.y + p1 * w1.y + b.y,
                               p0 * w0.z + p1 * w1.z + b.z,
                               p0 * w0.w + p1 * w1.w + b.w);
}

// layer-0 fused edge update + gated scatter  [rank-1 e0, no GEMM]
__global__ void layer0_edge_kernel(const float* __restrict__ ea, const int* __restrict__ src,
                                   const int* __restrict__ dst,
                                   const float* __restrict__ Wa, const float* __restrict__ ba,
                                   const float* __restrict__ be0, const float* __restrict__ prec,
                                   const fp16* __restrict__ xcat,
                                   fp16* __restrict__ Ch, fp16* __restrict__ Cl,
                                   float* __restrict__ agg) {
    int i = blockIdx.x * blockDim.x + threadIdx.x;
    if (i >= EE * 64) return;
    int m = i >> 6, c = i & 63;
    float a = ea[m];
    int s = src[m], d = dst[m];
    float4 wa = ((const float4*)Wa)[c];
    float4 bav = ((const float4*)ba)[c];
    float4 vv = ((const float4*)(prec + 3072))[c];
    float4 cc = ((const float4*)(prec + 3328))[c];
    float4 bev = ((const float4*)be0)[c];
    uint2 gsw = ((const uint2*)(xcat + (size_t)s * 1024 + 512))[c];
    uint2 gtw = ((const uint2*)(xcat + (size_t)d * 1024 + 768))[c];
    uint2 w2w = ((const uint2*)(xcat + (size_t)s * 1024 + 256))[c];
    float2 gs01 = unpack2(gsw.x), gs23 = unpack2(gsw.y);
    float2 gt01 = unpack2(gtw.x), gt23 = unpack2(gtw.y);
    float2 w201 = unpack2(w2w.x), w223 = unpack2(w2w.y);

    float e0 = a * wa.x + bav.x, e1 = a * wa.y + bav.y;
    float e2 = a * wa.z + bav.z, e3 = a * wa.w + bav.w;
    float v0 = e0 + fmaxf(a * vv.x + cc.x + gs01.x + gt01.x + bev.x, 0.f);
    float v1 = e1 + fmaxf(a * vv.y + cc.y + gs01.y + gt01.y + bev.y, 0.f);
    float v2 = e2 + fmaxf(a * vv.z + cc.z + gs23.x + gt23.x + bev.z, 0.f);
    float v3 = e3 + fmaxf(a * vv.w + cc.w + gs23.y + gt23.y + bev.w, 0.f);
    fp16 h0, l0, h1, l1, h2, l2, h3, l3;
    split2(v0, h0, l0); split2(v1, h1, l1); split2(v2, h2, l2); split2(v3, h3, l3);
    ((uint2*)Ch)[i] = make_uint2(pack2(h0, h1), pack2(h2, h3));
    ((uint2*)Cl)[i] = make_uint2(pack2(l0, l1), pack2(l2, l3));
    red_v4(agg + (size_t)d * 256 + c * 4,
           w201.x / (1.f + __expf(-e0)), w201.y / (1.f + __expf(-e1)),
           w223.x / (1.f + __expf(-e2)), w223.y / (1.f + __expf(-e3)));
}

__global__ void node_update_kernel(const float* __restrict__ x, const fp16* __restrict__ xcat,
                                   const float* __restrict__ agg, float* __restrict__ xo,
                                   fp16* __restrict__ xh, fp16* __restrict__ xl) {
    int i = blockIdx.x * blockDim.x + threadIdx.x;
    if (i >= NN * 64) return;
    int n = i >> 6, c = i & 63;
    float4 xv = ((const float4*)x)[i];
    uint2 wvw = ((const uint2*)(xcat + (size_t)n * 1024))[c];
    float2 wv01 = unpack2(wvw.x), wv23 = unpack2(wvw.y);
    float4 av = ((const float4*)agg)[i];
    float4 r;
    r.x = xv.x + fmaxf(wv01.x + av.x, 0.f);
    r.y = xv.y + fmaxf(wv01.y + av.y, 0.f);
    r.z = xv.z + fmaxf(wv23.x + av.z, 0.f);
    r.w = xv.w + fmaxf(wv23.y + av.w, 0.f);
    ((float4*)xo)[i] = r;
    fp16 h0, l0, h1, l1, h2, l2, h3, l3;
    split2(r.x, h0, l0); split2(r.y, h1, l1); split2(r.z, h2, l2); split2(r.w, h3, l3);
    ((uint2*)xh)[i] = make_uint2(pack2(h0, h1), pack2(h2, h3));
    ((uint2*)xl)[i] = make_uint2(pack2(l0, l1), pack2(l2, l3));
}

// ---------------- pipelined mma.sync split-fp16 GEMM ----------------
// 256 threads (8 warps, 2x4), CTA tile 128x128, warp tile 64x32.
// K=256 in 4 chunks of 64, cp.async double-buffered, 2 CTAs/SM (96KB each).
// SPLIT template: 1 = two-term (Ah+Al)@B, 0 = hi-only.
// mode 0: Cst[m*ldC+n] = fp16(D + bias)
// mode 1: edge residual + hi/lo re-split + gated scatter; Cl write optional.
// mode 2: fused MLP head (fp32 out)

#define OFF_AH 0
#define OFF_AL 16384
#define OFF_B  32768
#define BUF_STRIDE 49152
#define CS_LD 132
#define SMEM_TOTAL 98304

__device__ __forceinline__ void stage_tile(uint32_t sdst, const fp16* __restrict__ G,
                                           int r0, int rmax, int k0, int tid) {
#pragma unroll
    for (int t = 0; t < 4; t++) {
        int idx = tid + t * 256;
        int r = idx >> 3, c = idx & 7;
        int gr = r0 + r;
        const fp16* srcp = G + (size_t)gr * UU + k0 + c * 8;
        uint32_t dst = sdst + r * 128 + (((c ^ (r & 7))) << 4);
        int sz = (gr < rmax) ? 16 : 0;
        asm volatile("cp.async.cg.shared.global [%0], [%1], 16, %2;"
                     :: "r"(dst), "l"(srcp), "r"(sz));
    }
}

template <int SPLIT>
__global__ void __launch_bounds__(256, 2)
mma_gemm(const fp16* __restrict__ Ah, const fp16* __restrict__ Al,
         const fp16* __restrict__ Bw,
         int M, int mode,
         const float* __restrict__ bias, float* __restrict__ C,
         fp16* __restrict__ Cst, int ldC,
         const int* __restrict__ src, const int* __restrict__ dst,
         const fp16* __restrict__ gS, const fp16* __restrict__ gT, int gLd,
         const float* __restrict__ beL,
         fp16* __restrict__ Ch, fp16* __restrict__ Cl,
         const fp16* __restrict__ gW2, float* __restrict__ agg,
         const float* __restrict__ ea, const float* __restrict__ bm1,
         const float* __restrict__ alpha, const float* __restrict__ Wm1r,
         const float* __restrict__ Wm2, const float* __restrict__ bm2) {
    extern __shared__ __align__(1024) uint8_t smem_raw[];
    uint32_t sbase = smem_u32(smem_raw);
    int tid = threadIdx.x;
    int lane = tid & 31;
    int wid = tid >> 5;
    int wm = wid >> 2;
    int wn = wid & 3;
    int col0 = blockIdx.x * 128;
    int row0 = blockIdx.y * 128;

    float acc[4][4][4];
#pragma unroll
    for (int a = 0; a < 4; a++)
#pragma unroll
        for (int b = 0; b < 4; b++)
#pragma unroll
            for (int c = 0; c < 4; c++) acc[a][b][c] = 0.f;

    int arow = lane & 15;
    int achunk = lane >> 4;
    int brow = (lane & 7) + ((lane >> 4) << 3);
    int bchunk = (lane >> 3) & 1;

    stage_tile(sbase + OFF_AH, Ah, row0, M, 0, tid);
    if (SPLIT) stage_tile(sbase + OFF_AL, Al, row0, M, 0, tid);
    stage_tile(sbase + OFF_B, Bw, col0, 1 << 30, 0, tid);
    asm volatile("cp.async.commit_group;");

    for (int kc = 0; kc < 4; kc++) {
        if (kc < 3) {
            uint32_t nb = sbase + ((kc + 1) & 1) * BUF_STRIDE;
            int k0 = (kc + 1) * 64;
            stage_tile(nb + OFF_AH, Ah, row0, M, k0, tid);
            if (SPLIT) stage_tile(nb + OFF_AL, Al, row0, M, k0, tid);
            stage_tile(nb + OFF_B, Bw, col0, 1 << 30, k0, tid);
            asm volatile("cp.async.commit_group;");
            asm volatile("cp.async.wait_group 1;");
        } else {
            asm volatile("cp.async.wait_group 0;");
        }
        __syncthreads();

        uint32_t base = sbase + (kc & 1) * BUF_STRIDE;
#pragma unroll
        for (int kk = 0; kk < 4; kk++) {
            uint32_t bf[2][4];
#pragma unroll
            for (int nt2 = 0; nt2 < 2; nt2++) {
                int r = wn * 32 + nt2 * 16 + brow;
                int ch = kk * 2 + bchunk;
                uint32_t off = (uint32_t)(r * 128 + (((ch ^ (r & 7))) << 4));
                ldsm4(base + OFF_B + off, bf[nt2]);
            }
#pragma unroll
            for (int mt = 0; mt < 4; mt++) {
                int r = wm * 64 + mt * 16 + arow;
                int ch = kk * 2 + achunk;
                uint32_t off = (uint32_t)(r * 128 + (((ch ^ (r & 7))) << 4));
                uint32_t ah[4];
                ldsm4(base + OFF_AH + off, ah);
#pragma unroll
                for (int nt = 0; nt < 4; nt++)
                    mma16816(acc[mt][nt], ah, &bf[nt >> 1][(nt & 1) * 2]);
                if (SPLIT) {
                    uint32_t al[4];
                    ldsm4(base + OFF_AL + off, al);
#pragma unroll
                    for (int nt = 0; nt < 4; nt++)
                        mma16816(acc[mt][nt], al, &bf[nt >> 1][(nt & 1) * 2]);
                }
            }
        }
        __syncthreads();
    }

    float* Cs = (float*)smem_raw;
#pragma unroll
    for (int mt = 0; mt < 4; mt++) {
#pragma unroll
        for (int nt = 0; nt < 4; nt++) {
            int r = wm * 64 + mt * 16 + (lane >> 2);
            int cl = wn * 32 + nt * 8 + (lane & 3) * 2;
            Cs[r * CS_LD + cl] = acc[mt][nt][0];
            Cs[r * CS_LD + cl + 1] = acc[mt][nt][1];
            Cs[(r + 8) * CS_LD + cl] = acc[mt][nt][2];
            Cs[(r + 8) * CS_LD + cl + 1] = acc[mt][nt][3];
        }
    }
    __syncthreads();

    int nl = lane * 4;
#pragma unroll 1
    for (int it = 0; it < 16; it++) {
        int r = wid * 16 + it;
        int m = row0 + r;
        if (m >= M) continue;
        const float* crow = Cs + r * CS_LD;
        int n = col0 + nl;
        if (mode == 0) {
            float4 v = *(const float4*)&crow[nl];
            if (bias) {
                float4 b4 = *(const float4*)&bias[n];
                v.x += b4.x; v.y += b4.y; v.z += b4.z; v.w += b4.w;
            }
            *(uint2*)&Cst[(size_t)m * ldC + n] = pack4f(v.x, v.y, v.z, v.w);
        } else if (mode == 1) {
            int sIdx = src[m], dIdx = dst[m];
            float4 d4 = *(const float4*)&crow[nl];
            uint2 hb = *(const uint2*)&Ah[(size_t)m * 256 + n];
            uint2 lb = *(const uint2*)&Al[(size_t)m * 256 + n];
            float2 h01 = unpack2(hb.x), h23 = unpack2(hb.y);
            float2 l01 = unpack2(lb.x), l23 = unpack2(lb.y);
            float e0 = h01.x + l01.x, e1 = h01.y + l01.y;
            float e2 = h23.x + l23.x, e3 = h23.y + l23.y;
            uint2 gsw = *(const uint2*)&gS[(size_t)sIdx * gLd + n];
            uint2 gtw = *(const uint2*)&gT[(size_t)dIdx * gLd + n];
            float2 gs01 = unpack2(gsw.x), gs23 = unpack2(gsw.y);
            float2 gt01 = unpack2(gtw.x), gt23 = unpack2(gtw.y);
            float4 be4 = *(const float4*)&beL[n];
            float v0 = e0 + fmaxf(d4.x + gs01.x + gt01.x + be4.x, 0.f);
            float v1 = e1 + fmaxf(d4.y + gs01.y + gt01.y + be4.y, 0.f);
            float v2 = e2 + fmaxf(d4.z + gs23.x + gt23.x + be4.z, 0.f);
            float v3 = e3 + fmaxf(d4.w + gs23.y + gt23.y + be4.w, 0.f);
            fp16 h0, l0, h1, l1, h2, l2, h3, l3;
            split2(v0, h0, l0); split2(v1, h1, l1);
            split2(v2, h2, l2); split2(v3, h3, l3);
            *(uint2*)&Ch[(size_t)m * 256 + n] = make_uint2(pack2(h0, h1), pack2(h2, h3));
            if (Cl)  // dead at l=3 (head reads hi only)
                *(uint2*)&Cl[(size_t)m * 256 + n] = make_uint2(pack2(l0, l1), pack2(l2, l3));
            if (gW2) {
                uint2 w2w = *(const uint2*)&gW2[(size_t)sIdx * gLd + n];
                float2 w201 = unpack2(w2w.x), w223 = unpack2(w2w.y);
                red_v4(agg + (size_t)dIdx * 256 + n,
                       w201.x / (1.f + __expf(-e0)), w201.y / (1.f + __expf(-e1)),
                       w223.x / (1.f + __expf(-e2)), w223.y / (1.f + __expf(-e3)));
            }
        } else {
            float alpha0 = alpha[0];
            float eam = ea[m];
            float4 d4 = *(const float4*)&crow[nl];
            float4 wr = *(const float4*)&Wm1r[nl];
            float4 bb = *(const float4*)&bm1[nl];
            float4 w2 = *(const float4*)&Wm2[nl];
            float h0 = d4.x + eam * wr.x + bb.x;
            float h1 = d4.y + eam * wr.y + bb.y;
            float h2 = d4.z + eam * wr.z + bb.z;
            float h3 = d4.w + eam * wr.w + bb.w;
            h0 = (h0 > 0.f) ? h0 : alpha0 * h0;
            h1 = (h1 > 0.f) ? h1 : alpha0 * h1;
            h2 = (h2 > 0.f) ? h2 : alpha0 * h2;
            h3 = (h3 > 0.f) ? h3 : alpha0 * h3;
            float partial = h0 * w2.x + h1 * w2.y + h2 * w2.z + h3 * w2.w;
#pragma unroll
            for (int s = 16; s > 0; s >>= 1)
                partial += __shfl_xor_sync(0xffffffffu, partial, s);
            if (lane == 0) C[m] = partial + bm2[0];
        }
    }
}

// ---------------- host ----------------

static void mma_launch(int split,
                       const fp16* Ah, const fp16* Al, const fp16* Bw,
                       int M, int Nc, int mode,
                       const float* bias, float* C, fp16* Cst, int ldC,
                       const int* src = nullptr, const int* dst = nullptr,
                       const fp16* gS = nullptr, const fp16* gT = nullptr, int gLd = 0,
                       const float* beL = nullptr,
                       fp16* Ch = nullptr, fp16* Cl = nullptr,
                       const fp16* gW2 = nullptr, float* agg = nullptr,
                       const float* ea = nullptr, const float* bm1 = nullptr,
                       const float* alpha = nullptr, const float* Wm1r = nullptr,
                       const float* Wm2 = nullptr, const float* bm2 = nullptr) {
    dim3 grid(Nc / 128, (M + 127) / 128);
    if (split)
        mma_gemm<1><<<grid, 256, SMEM_TOTAL>>>(Ah, Al, Bw, M, mode, bias, C, Cst, ldC,
                                               src, dst, gS, gT, gLd, beL, Ch, Cl,
                                               gW2, agg, ea, bm1, alpha, Wm1r, Wm2, bm2);
    else
        mma_gemm<0><<<grid, 256, SMEM_TOTAL>>>(Ah, Al, Bw, M, mode, bias, C, Cst, ldC,
                                               src, dst, gS, gT, gLd, beL, Ch, Cl,
                                               gW2, agg, ea, bm1, alpha, Wm1r, Wm2, bm2);
}

extern "C" void kernel_launch(void* const* d_in, const int* in_sizes, int n_in,
                              void* d_out, int out_size) {
    const float* pos   = (const float*)d_in[0];
    const float* ea    = (const float*)d_in[1];
    const int*   ei    = (const int*)d_in[2];
    const float* Wp    = (const float*)d_in[3];
    const float* bp    = (const float*)d_in[4];
    const float* Wa    = (const float*)d_in[5];
    const float* ba    = (const float*)d_in[6];
    const float* W1    = (const float*)d_in[7];
    const float* b1    = (const float*)d_in[8];
    const float* W2    = (const float*)d_in[9];
    const float* b2    = (const float*)d_in[10];
    const float* We    = (const float*)d_in[11];
    const float* be    = (const float*)d_in[12];
    const float* Ws    = (const float*)d_in[13];
    const float* Wt    = (const float*)d_in[14];
    const float* Wm1   = (const float*)d_in[15];
    const float* bm1   = (const float*)d_in[16];
    const float* alpha = (const float*)d_in[17];
    const float* Wm2   = (const float*)d_in[18];
    const float* bm2   = (const float*)d_in[19];
    float* out = (float*)d_out;

    const int* src = ei;
    const int* dst = ei + EE;

    cudaFuncSetAttribute(mma_gemm<1>, cudaFuncAttributeMaxDynamicSharedMemorySize, SMEM_TOTAL);
    cudaFuncSetAttribute(mma_gemm<0>, cudaFuncAttributeMaxDynamicSharedMemorySize, SMEM_TOTAL);

    float *xA, *xB, *agg, *bcat, *prec;
    fp16 *ehA, *elA, *ehB, *elB, *xh, *xl, *xcat, *Bw;
    cudaGetSymbolAddress((void**)&ehA, g_ehA);
    cudaGetSymbolAddress((void**)&elA, g_elA);
    cudaGetSymbolAddress((void**)&ehB, g_ehB);
    cudaGetSymbolAddress((void**)&elB, g_elB);
    cudaGetSymbolAddress((void**)&xA, g_xA);
    cudaGetSymbolAddress((void**)&xB, g_xB);
    cudaGetSymbolAddress((void**)&xh, g_xh);
    cudaGetSymbolAddress((void**)&xl, g_xl);
    cudaGetSymbolAddress((void**)&xcat, g_xcat);
    cudaGetSymbolAddress((void**)&agg, g_agg);
    cudaGetSymbolAddress((void**)&Bw, g_Bw);
    cudaGetSymbolAddress((void**)&bcat, g_bcat);
    cudaGetSymbolAddress((void**)&prec, g_prec);

    const int TB = 256;
    const int SLOT = UU * UU;

    int convN = 18 * 65536 + 32768 + 3072;
    convert_all_kernel<<<(convN + TB - 1) / TB, TB>>>(W1, W2, Ws, Wt, We, Wm1,
                                                      b1, b2, Bw, bcat);
    precompute_kernel<<<(3584 + TB - 1) / TB, TB>>>(Wa, ba, We, Wp, bp,
                                                    W1, W2, Ws, Wt, b1, b2, prec);
    init_x_kernel<<<(NN * 64 + TB - 1) / TB, TB>>>(pos, Wp, bp, xA);

    // --- layer 0 (rank-collapsed; no GEMMs) ---
    zero_kernel<<<(NN * 64 + TB - 1) / TB, TB>>>((float4*)agg, NN * 64);
    layer0_node_kernel<<<(NN * 256 + TB - 1) / TB, TB>>>(pos, prec, xcat);
    layer0_edge_kernel<<<(EE * 64 + TB - 1) / TB, TB>>>(ea, src, dst, Wa, ba, be,
                                                        prec, xcat, ehA, elA, agg);
    node_update_kernel<<<(NN * 64 + TB - 1) / TB, TB>>>(xA, xcat, agg, xB, xh, xl);

    float* xc = xB; float* xn = xA;
    fp16 *ehc = ehA, *elc = elA, *ehn = ehB, *eln = elB;

    // --- layers 1, 2 (split=1 — measured best; MMA doubles as latency filler) ---
    for (int l = 1; l < 3; l++) {
        zero_kernel<<<(NN * 64 + TB - 1) / TB, TB>>>((float4*)agg, NN * 64);
        mma_launch(1, xh, xl, Bw + (l * 5) * SLOT,
                   NN, 1024, 0, bcat + l * 1024, nullptr, xcat, 1024);
        mma_launch(1, ehc, elc, Bw + (l * 5 + 4) * SLOT,
                   EE, 256, 1, nullptr, nullptr, nullptr, 0,
                   src, dst, xcat + 512, xcat + 768, 1024,
                   be + l * 256, ehn, eln,
                   xcat + 256, agg);
        node_update_kernel<<<(NN * 64 + TB - 1) / TB, TB>>>(xc, xcat, agg, xn, xh, xl);
        { float* t = xc; xc = xn; xn = t; }
        { fp16* t = ehc; ehc = ehn; ehn = t; }
        { fp16* t = elc; elc = eln; eln = t; }
    }

    // --- final edge update (l=3): lo output is DEAD (head reads hi only) ---
    mma_launch(1, xh, xl, Bw + 15 * SLOT,
               NN, 512, 0, nullptr, nullptr, xcat, 1024);
    mma_launch(1, ehc, elc, Bw + 17 * SLOT,
               EE, 256, 1, nullptr, nullptr, nullptr, 0,
               src, dst, xcat, xcat + 256, 1024,
               be + 3 * 256, ehn, /*Cl=*/nullptr,
               nullptr, nullptr);
    { fp16* t = ehc; ehc = ehn; ehn = t; }

    // --- fused MLP head (single col tile, hi-only A, direct store) ---
    mma_launch(0, ehc, nullptr, Bw + 18 * SLOT,
               EE, 128, 2, nullptr, out, nullptr, 0,
               nullptr, nullptr, nullptr, nullptr, 0, nullptr,
               nullptr, nullptr, nullptr, nullptr,
               ea, bm1, alpha, Wm1 + 256 * 128, Wm2, bm2);

    (void)in_sizes; (void)n_in; (void)out_size;
}

// round 17
// speedup vs baseline: 1.1029x; 1.0061x over previous
#include <cuda_runtime.h>
#include <cuda_fp16.h>
#include <stdint.h>
#include <math.h>

#define NN 10000
#define EE 320000
#define UU 256

typedef __half fp16;

// ---------------- static device scratch ----------------
__device__ fp16  g_ehA[EE * UU];
__device__ fp16  g_elA[EE * UU];
__device__ fp16  g_ehB[EE * UU];
__device__ fp16  g_elB[EE * UU];
__device__ float g_xA[NN * UU];
__device__ float g_xB[NN * UU];
__device__ fp16  g_xh[NN * UU];
__device__ fp16  g_xl[NN * UU];
__device__ fp16  g_xcat[NN * 1024];    // fp16 node-GEMM outputs [xW1|xW2|xWs|xWt]
__device__ float g_agg[NN * UU];
__device__ fp16  g_Bw[19 * UU * UU];   // transposed [N,K] single-fp16 weight slots
__device__ float g_bcat[3 * 1024];
__device__ float g_prec[3584];         // layer-0 rank-collapse precomputes

// ---------------- helpers ----------------
__device__ __forceinline__ uint32_t smem_u32(const void* p) {
    uint32_t a;
    asm("{ .reg .u64 t; cvta.to.shared.u64 t, %1; cvt.u32.u64 %0, t; }" : "=r"(a) : "l"(p));
    return a;
}
__device__ __forceinline__ void ldsm4(uint32_t addr, uint32_t* r) {
    asm volatile("ldmatrix.sync.aligned.m8n8.x4.shared.b16 {%0,%1,%2,%3}, [%4];"
                 : "=r"(r[0]), "=r"(r[1]), "=r"(r[2]), "=r"(r[3]) : "r"(addr));
}
__device__ __forceinline__ void mma16816(float* c, const uint32_t* a, const uint32_t* b) {
    asm volatile(
        "mma.sync.aligned.m16n8k16.row.col.f32.f16.f16.f32 "
        "{%0,%1,%2,%3}, {%4,%5,%6,%7}, {%8,%9}, {%0,%1,%2,%3};"
        : "+f"(c[0]), "+f"(c[1]), "+f"(c[2]), "+f"(c[3])
        : "r"(a[0]), "r"(a[1]), "r"(a[2]), "r"(a[3]), "r"(b[0]), "r"(b[1]));
}
__device__ __forceinline__ void red_v4(float* addr, float a, float b, float c, float d) {
    asm volatile("red.global.add.v4.f32 [%0], {%1, %2, %3, %4};"
                 :: "l"(addr), "f"(a), "f"(b), "f"(c), "f"(d) : "memory");
}
__device__ __forceinline__ void st_cs_u2(void* addr, uint2 v) {
    asm volatile("st.global.cs.v2.u32 [%0], {%1, %2};"
                 :: "l"(addr), "r"(v.x), "r"(v.y) : "memory");
}
__device__ __forceinline__ void split2(float v, fp16& h, fp16& l) {
    h = __float2half_rn(v);
    l = __float2half_rn(v - __half2float(h));
}
__device__ __forceinline__ float2 unpack2(uint32_t w) {
    __half2 h = *reinterpret_cast<__half2*>(&w);
    return __half22float2(h);
}
__device__ __forceinline__ uint32_t pack2(fp16 a, fp16 b) {
    __half2 h = __halves2half2(a, b);
    return *reinterpret_cast<uint32_t*>(&h);
}
__device__ __forceinline__ uint2 pack4f(float a, float b, float c, float d) {
    return make_uint2(pack2(__float2half_rn(a), __float2half_rn(b)),
                      pack2(__float2half_rn(c), __float2half_rn(d)));
}

// ---------------- prep kernels ----------------

__global__ void zero_kernel(float4* __restrict__ p, int n4) {
    int i = blockIdx.x * blockDim.x + threadIdx.x;
    if (i < n4) p[i] = make_float4(0.f, 0.f, 0.f, 0.f);
}

__global__ void convert_all_kernel(const float* __restrict__ W1, const float* __restrict__ W2,
                                   const float* __restrict__ Ws, const float* __restrict__ Wt,
                                   const float* __restrict__ We, const float* __restrict__ Wm1,
                                   const float* __restrict__ b1, const float* __restrict__ b2,
                                   fp16* __restrict__ Bw, float* __restrict__ bcat) {
    int i = blockIdx.x * blockDim.x + threadIdx.x;
    const int SQ = 18 * 65536;
    if (i < SQ) {
        int s = i >> 16, w = i & 65535;
        int k = w >> 8, n = w & 255;
        const float* srcp;
        if (s < 15) {
            int l = s / 5, t = s - l * 5;
            const float* bases[5] = {W1, W2, Ws, Wt, We};
            srcp = bases[t] + l * 65536;
        } else if (s == 15) srcp = Ws + 3 * 65536;
        else if (s == 16) srcp = Wt + 3 * 65536;
        else srcp = We + 3 * 65536;
        Bw[s * 65536 + n * 256 + k] = __float2half_rn(srcp[k * 256 + n]);
    } else if (i < SQ + 32768) {
        int w = i - SQ;
        int k = w >> 7, n = w & 127;
        Bw[18 * 65536 + n * 256 + k] = __float2half_rn(Wm1[k * 128 + n]);
    } else if (i < SQ + 32768 + 3072) {
        int w = i - SQ - 32768;
        int l = w >> 10, j = w & 1023;
        float v = 0.f;
        if (j < 256) v = b1[l * 256 + j];
        else if (j < 512) v = b2[l * 256 + (j - 256)];
        bcat[w] = v;
    }
}

// rank-collapse precomputes for layer 0
__global__ void precompute_kernel(const float* __restrict__ Wa, const float* __restrict__ ba,
                                  const float* __restrict__ We, const float* __restrict__ Wp,
                                  const float* __restrict__ bp,
                                  const float* __restrict__ W1, const float* __restrict__ W2,
                                  const float* __restrict__ Ws, const float* __restrict__ Wt,
                                  const float* __restrict__ b1, const float* __restrict__ b2,
                                  float* __restrict__ prec) {
    int n = blockIdx.x * blockDim.x + threadIdx.x;
    if (n >= 3584) return;
    if (n < 2048) {
        int p = n >> 10, col = n & 1023;
        const float* W = (col < 256) ? W1 : (col < 512) ? W2 : (col < 768) ? Ws : Wt;
        int nn = col & 255;
        float s = 0.f;
        for (int k = 0; k < 256; k++) s += Wp[p * 256 + k] * W[k * 256 + nn];
        prec[p * 1024 + col] = s;
    } else if (n < 3072) {
        int col = n - 2048;
        const float* W = (col < 256) ? W1 : (col < 512) ? W2 : (col < 768) ? Ws : Wt;
        int nn = col & 255;
        float s = 0.f;
        for (int k = 0; k < 256; k++) s += bp[k] * W[k * 256 + nn];
        if (col < 256) s += b1[col];
        else if (col < 512) s += b2[col - 256];
        prec[2048 + col] = s;
    } else if (n < 3328) {
        int nn = n - 3072;
        float s = 0.f;
        for (int k = 0; k < 256; k++) s += Wa[k] * We[k * 256 + nn];
        prec[3072 + nn] = s;
    } else {
        int nn = n - 3328;
        float s = 0.f;
        for (int k = 0; k < 256; k++) s += ba[k] * We[k * 256 + nn];
        prec[3328 + nn] = s;
    }
}

__global__ void init_x_kernel(const float* __restrict__ pos, const float* __restrict__ Wp,
                              const float* __restrict__ bp, float* __restrict__ x) {
    int i = blockIdx.x * blockDim.x + threadIdx.x;
    if (i >= NN * 64) return;
    int n = i >> 6, c = i & 63;
    float p0 = pos[n * 2 + 0], p1 = pos[n * 2 + 1];
    float4 w0 = ((const float4*)Wp)[c];
    float4 w1 = ((const float4*)Wp)[64 + c];
    float4 b = ((const float4*)bp)[c];
    float4 r;
    r.x = p0 * w0.x + p1 * w1.x + b.x;
    r.y = p0 * w0.y + p1 * w1.y + b.y;
    r.z = p0 * w0.z + p1 * w1.z + b.z;
    r.w = p0 * w0.w + p1 * w1.w + b.w;
    ((float4*)x)[i] = r;
}

// xcat0 = fp16(pos @ (Wp@Wcat0) + (bp@Wcat0 + bcat0))    [rank-2, no GEMM]
__global__ void layer0_node_kernel(const float* __restrict__ pos, const float* __restrict__ prec,
                                   fp16* __restrict__ xcat) {
    int i = blockIdx.x * blockDim.x + threadIdx.x;
    if (i >= NN * 256) return;
    int n = i >> 8, c = i & 255;
    float p0 = pos[n * 2 + 0], p1 = pos[n * 2 + 1];
    float4 w0 = ((const float4*)prec)[c];
    float4 w1 = ((const float4*)(prec + 1024))[c];
    float4 b = ((const float4*)(prec + 2048))[c];
    ((uint2*)xcat)[i] = pack4f(p0 * w0.x + p1 * w1.x + b.x,
                               p0 * w0.y + p1 * w1.y + b.y,
                               p0 * w0.z + p1 * w1.z + b.z,
                               p0 * w0.w + p1 * w1.w + b.w);
}

// layer-0 fused edge update + gated scatter  [rank-1 e0, no GEMM]
__global__ void layer0_edge_kernel(const float* __restrict__ ea, const int* __restrict__ src,
                                   const int* __restrict__ dst,
                                   const float* __restrict__ Wa, const float* __restrict__ ba,
                                   const float* __restrict__ be0, const float* __restrict__ prec,
                                   const fp16* __restrict__ xcat,
                                   fp16* __restrict__ Ch, fp16* __restrict__ Cl,
                                   float* __restrict__ agg) {
    int i = blockIdx.x * blockDim.x + threadIdx.x;
    if (i >= EE * 64) return;
    int m = i >> 6, c = i & 63;
    float a = ea[m];
    int s = src[m], d = dst[m];
    float4 wa = ((const float4*)Wa)[c];
    float4 bav = ((const float4*)ba)[c];
    float4 vv = ((const float4*)(prec + 3072))[c];
    float4 cc = ((const float4*)(prec + 3328))[c];
    float4 bev = ((const float4*)be0)[c];
    uint2 gsw = ((const uint2*)(xcat + (size_t)s * 1024 + 512))[c];
    uint2 gtw = ((const uint2*)(xcat + (size_t)d * 1024 + 768))[c];
    uint2 w2w = ((const uint2*)(xcat + (size_t)s * 1024 + 256))[c];
    float2 gs01 = unpack2(gsw.x), gs23 = unpack2(gsw.y);
    float2 gt01 = unpack2(gtw.x), gt23 = unpack2(gtw.y);
    float2 w201 = unpack2(w2w.x), w223 = unpack2(w2w.y);

    float e0 = a * wa.x + bav.x, e1 = a * wa.y + bav.y;
    float e2 = a * wa.z + bav.z, e3 = a * wa.w + bav.w;
    float v0 = e0 + fmaxf(a * vv.x + cc.x + gs01.x + gt01.x + bev.x, 0.f);
    float v1 = e1 + fmaxf(a * vv.y + cc.y + gs01.y + gt01.y + bev.y, 0.f);
    float v2 = e2 + fmaxf(a * vv.z + cc.z + gs23.x + gt23.x + bev.z, 0.f);
    float v3 = e3 + fmaxf(a * vv.w + cc.w + gs23.y + gt23.y + bev.w, 0.f);
    fp16 h0, l0, h1, l1, h2, l2, h3, l3;
    split2(v0, h0, l0); split2(v1, h1, l1); split2(v2, h2, l2); split2(v3, h3, l3);
    st_cs_u2(&((uint2*)Ch)[i], make_uint2(pack2(h0, h1), pack2(h2, h3)));
    st_cs_u2(&((uint2*)Cl)[i], make_uint2(pack2(l0, l1), pack2(l2, l3)));
    red_v4(agg + (size_t)d * 256 + c * 4,
           w201.x / (1.f + __expf(-e0)), w201.y / (1.f + __expf(-e1)),
           w223.x / (1.f + __expf(-e2)), w223.y / (1.f + __expf(-e3)));
}

// x_new = x + relu(xcat[:,0:256] + agg); emits fp16 hi/lo; ZEROES agg for next layer.
__global__ void node_update_kernel(const float* __restrict__ x, const fp16* __restrict__ xcat,
                                   float* __restrict__ agg, float* __restrict__ xo,
                                   fp16* __restrict__ xh, fp16* __restrict__ xl) {
    int i = blockIdx.x * blockDim.x + threadIdx.x;
    if (i >= NN * 64) return;
    int n = i >> 6, c = i & 63;
    float4 xv = ((const float4*)x)[i];
    uint2 wvw = ((const uint2*)(xcat + (size_t)n * 1024))[c];
    float2 wv01 = unpack2(wvw.x), wv23 = unpack2(wvw.y);
    float4 av = ((float4*)agg)[i];
    ((float4*)agg)[i] = make_float4(0.f, 0.f, 0.f, 0.f);   // ready for next layer's scatter
    float4 r;
    r.x = xv.x + fmaxf(wv01.x + av.x, 0.f);
    r.y = xv.y + fmaxf(wv01.y + av.y, 0.f);
    r.z = xv.z + fmaxf(wv23.x + av.z, 0.f);
    r.w = xv.w + fmaxf(wv23.y + av.w, 0.f);
    ((float4*)xo)[i] = r;
    fp16 h0, l0, h1, l1, h2, l2, h3, l3;
    split2(r.x, h0, l0); split2(r.y, h1, l1); split2(r.z, h2, l2); split2(r.w, h3, l3);
    ((uint2*)xh)[i] = make_uint2(pack2(h0, h1), pack2(h2, h3));
    ((uint2*)xl)[i] = make_uint2(pack2(l0, l1), pack2(l2, l3));
}

// ---------------- pipelined mma.sync split-fp16 GEMM ----------------
// 256 threads (8 warps, 2x4), CTA tile 128x128, warp tile 64x32.
// K=256 in 4 chunks of 64, cp.async double-buffered, 2 CTAs/SM (96KB each).
// SPLIT template: 1 = two-term (Ah+Al)@B, 0 = hi-only.
// mode 0: Cst = fp16(D + bias);  mode 1: edge residual (streaming Ch/Cl) + scatter;
// mode 2: fused MLP head.

#define OFF_AH 0
#define OFF_AL 16384
#define OFF_B  32768
#define BUF_STRIDE 49152
#define CS_LD 132
#define SMEM_TOTAL 98304

__device__ __forceinline__ void stage_tile(uint32_t sdst, const fp16* __restrict__ G,
                                           int r0, int rmax, int k0, int tid) {
#pragma unroll
    for (int t = 0; t < 4; t++) {
        int idx = tid + t * 256;
        int r = idx >> 3, c = idx & 7;
        int gr = r0 + r;
        const fp16* srcp = G + (size_t)gr * UU + k0 + c * 8;
        uint32_t dst = sdst + r * 128 + (((c ^ (r & 7))) << 4);
        int sz = (gr < rmax) ? 16 : 0;
        asm volatile("cp.async.cg.shared.global [%0], [%1], 16, %2;"
                     :: "r"(dst), "l"(srcp), "r"(sz));
    }
}

template <int SPLIT>
__global__ void __launch_bounds__(256, 2)
mma_gemm(const fp16* __restrict__ Ah, const fp16* __restrict__ Al,
         const fp16* __restrict__ Bw,
         int M, int mode,
         const float* __restrict__ bias, float* __restrict__ C,
         fp16* __restrict__ Cst, int ldC,
         const int* __restrict__ src, const int* __restrict__ dst,
         const fp16* __restrict__ gS, const fp16* __restrict__ gT, int gLd,
         const float* __restrict__ beL,
         fp16* __restrict__ Ch, fp16* __restrict__ Cl,
         const fp16* __restrict__ gW2, float* __restrict__ agg,
         const float* __restrict__ ea, const float* __restrict__ bm1,
         const float* __restrict__ alpha, const float* __restrict__ Wm1r,
         const float* __restrict__ Wm2, const float* __restrict__ bm2) {
    extern __shared__ __align__(1024) uint8_t smem_raw[];
    uint32_t sbase = smem_u32(smem_raw);
    int tid = threadIdx.x;
    int lane = tid & 31;
    int wid = tid >> 5;
    int wm = wid >> 2;
    int wn = wid & 3;
    int col0 = blockIdx.x * 128;
    int row0 = blockIdx.y * 128;

    float acc[4][4][4];
#pragma unroll
    for (int a = 0; a < 4; a++)
#pragma unroll
        for (int b = 0; b < 4; b++)
#pragma unroll
            for (int c = 0; c < 4; c++) acc[a][b][c] = 0.f;

    int arow = lane & 15;
    int achunk = lane >> 4;
    int brow = (lane & 7) + ((lane >> 4) << 3);
    int bchunk = (lane >> 3) & 1;

    stage_tile(sbase + OFF_AH, Ah, row0, M, 0, tid);
    if (SPLIT) stage_tile(sbase + OFF_AL, Al, row0, M, 0, tid);
    stage_tile(sbase + OFF_B, Bw, col0, 1 << 30, 0, tid);
    asm volatile("cp.async.commit_group;");

    for (int kc = 0; kc < 4; kc++) {
        if (kc < 3) {
            uint32_t nb = sbase + ((kc + 1) & 1) * BUF_STRIDE;
            int k0 = (kc + 1) * 64;
            stage_tile(nb + OFF_AH, Ah, row0, M, k0, tid);
            if (SPLIT) stage_tile(nb + OFF_AL, Al, row0, M, k0, tid);
            stage_tile(nb + OFF_B, Bw, col0, 1 << 30, k0, tid);
            asm volatile("cp.async.commit_group;");
            asm volatile("cp.async.wait_group 1;");
        } else {
            asm volatile("cp.async.wait_group 0;");
        }
        __syncthreads();

        uint32_t base = sbase + (kc & 1) * BUF_STRIDE;
#pragma unroll
        for (int kk = 0; kk < 4; kk++) {
            uint32_t bf[2][4];
#pragma unroll
            for (int nt2 = 0; nt2 < 2; nt2++) {
                int r = wn * 32 + nt2 * 16 + brow;
                int ch = kk * 2 + bchunk;
                uint32_t off = (uint32_t)(r * 128 + (((ch ^ (r & 7))) << 4));
                ldsm4(base + OFF_B + off, bf[nt2]);
            }
#pragma unroll
            for (int mt = 0; mt < 4; mt++) {
                int r = wm * 64 + mt * 16 + arow;
                int ch = kk * 2 + achunk;
                uint32_t off = (uint32_t)(r * 128 + (((ch ^ (r & 7))) << 4));
                uint32_t ah[4];
                ldsm4(base + OFF_AH + off, ah);
#pragma unroll
                for (int nt = 0; nt < 4; nt++)
                    mma16816(acc[mt][nt], ah, &bf[nt >> 1][(nt & 1) * 2]);
                if (SPLIT) {
                    uint32_t al[4];
                    ldsm4(base + OFF_AL + off, al);
#pragma unroll
                    for (int nt = 0; nt < 4; nt++)
                        mma16816(acc[mt][nt], al, &bf[nt >> 1][(nt & 1) * 2]);
                }
            }
        }
        __syncthreads();
    }

    float* Cs = (float*)smem_raw;
#pragma unroll
    for (int mt = 0; mt < 4; mt++) {
#pragma unroll
        for (int nt = 0; nt < 4; nt++) {
            int r = wm * 64 + mt * 16 + (lane >> 2);
            int cl = wn * 32 + nt * 8 + (lane & 3) * 2;
            Cs[r * CS_LD + cl] = acc[mt][nt][0];
            Cs[r * CS_LD + cl + 1] = acc[mt][nt][1];
            Cs[(r + 8) * CS_LD + cl] = acc[mt][nt][2];
            Cs[(r + 8) * CS_LD + cl + 1] = acc[mt][nt][3];
        }
    }
    __syncthreads();

    int nl = lane * 4;
#pragma unroll 1
    for (int it = 0; it < 16; it++) {
        int r = wid * 16 + it;
        int m = row0 + r;
        if (m >= M) continue;
        const float* crow = Cs + r * CS_LD;
        int n = col0 + nl;
        if (mode == 0) {
            float4 v = *(const float4*)&crow[nl];
            if (bias) {
                float4 b4 = *(const float4*)&bias[n];
                v.x += b4.x; v.y += b4.y; v.z += b4.z; v.w += b4.w;
            }
            *(uint2*)&Cst[(size_t)m * ldC + n] = pack4f(v.x, v.y, v.z, v.w);
        } else if (mode == 1) {
            int sIdx = src[m], dIdx = dst[m];
            float4 d4 = *(const float4*)&crow[nl];
            uint2 hb = *(const uint2*)&Ah[(size_t)m * 256 + n];
            uint2 lb = *(const uint2*)&Al[(size_t)m * 256 + n];
            float2 h01 = unpack2(hb.x), h23 = unpack2(hb.y);
            float2 l01 = unpack2(lb.x), l23 = unpack2(lb.y);
            float e0 = h01.x + l01.x, e1 = h01.y + l01.y;
            float e2 = h23.x + l23.x, e3 = h23.y + l23.y;
            uint2 gsw = *(const uint2*)&gS[(size_t)sIdx * gLd + n];
            uint2 gtw = *(const uint2*)&gT[(size_t)dIdx * gLd + n];
            float2 gs01 = unpack2(gsw.x), gs23 = unpack2(gsw.y);
            float2 gt01 = unpack2(gtw.x), gt23 = unpack2(gtw.y);
            float4 be4 = *(const float4*)&beL[n];
            float v0 = e0 + fmaxf(d4.x + gs01.x + gt01.x + be4.x, 0.f);
            float v1 = e1 + fmaxf(d4.y + gs01.y + gt01.y + be4.y, 0.f);
            float v2 = e2 + fmaxf(d4.z + gs23.x + gt23.x + be4.z, 0.f);
            float v3 = e3 + fmaxf(d4.w + gs23.y + gt23.y + be4.w, 0.f);
            fp16 h0, l0, h1, l1, h2, l2, h3, l3;
            split2(v0, h0, l0); split2(v1, h1, l1);
            split2(v2, h2, l2); split2(v3, h3, l3);
            st_cs_u2(&Ch[(size_t)m * 256 + n], make_uint2(pack2(h0, h1), pack2(h2, h3)));
            if (Cl)  // dead at l=3 (head reads hi only)
                st_cs_u2(&Cl[(size_t)m * 256 + n], make_uint2(pack2(l0, l1), pack2(l2, l3)));
            if (gW2) {
                uint2 w2w = *(const uint2*)&gW2[(size_t)sIdx * gLd + n];
                float2 w201 = unpack2(w2w.x), w223 = unpack2(w2w.y);
                red_v4(agg + (size_t)dIdx * 256 + n,
                       w201.x / (1.f + __expf(-e0)), w201.y / (1.f + __expf(-e1)),
                       w223.x / (1.f + __expf(-e2)), w223.y / (1.f + __expf(-e3)));
            }
        } else {
            float alpha0 = alpha[0];
            float eam = ea[m];
            float4 d4 = *(const float4*)&crow[nl];
            float4 wr = *(const float4*)&Wm1r[nl];
            float4 bb = *(const float4*)&bm1[nl];
            float4 w2 = *(const float4*)&Wm2[nl];
            float h0 = d4.x + eam * wr.x + bb.x;
            float h1 = d4.y + eam * wr.y + bb.y;
            float h2 = d4.z + eam * wr.z + bb.z;
            float h3 = d4.w + eam * wr.w + bb.w;
            h0 = (h0 > 0.f) ? h0 : alpha0 * h0;
            h1 = (h1 > 0.f) ? h1 : alpha0 * h1;
            h2 = (h2 > 0.f) ? h2 : alpha0 * h2;
            h3 = (h3 > 0.f) ? h3 : alpha0 * h3;
            float partial = h0 * w2.x + h1 * w2.y + h2 * w2.z + h3 * w2.w;
#pragma unroll
            for (int s = 16; s > 0; s >>= 1)
                partial += __shfl_xor_sync(0xffffffffu, partial, s);
            if (lane == 0) C[m] = partial + bm2[0];
        }
    }
}

// ---------------- host ----------------

static void mma_launch(int split,
                       const fp16* Ah, const fp16* Al, const fp16* Bw,
                       int M, int Nc, int mode,
                       const float* bias, float* C, fp16* Cst, int ldC,
                       const int* src = nullptr, const int* dst = nullptr,
                       const fp16* gS = nullptr, const fp16* gT = nullptr, int gLd = 0,
                       const float* beL = nullptr,
                       fp16* Ch = nullptr, fp16* Cl = nullptr,
                       const fp16* gW2 = nullptr, float* agg = nullptr,
                       const float* ea = nullptr, const float* bm1 = nullptr,
                       const float* alpha = nullptr, const float* Wm1r = nullptr,
                       const float* Wm2 = nullptr, const float* bm2 = nullptr) {
    dim3 grid(Nc / 128, (M + 127) / 128);
    if (split)
        mma_gemm<1><<<grid, 256, SMEM_TOTAL>>>(Ah, Al, Bw, M, mode, bias, C, Cst, ldC,
                                               src, dst, gS, gT, gLd, beL, Ch, Cl,
                                               gW2, agg, ea, bm1, alpha, Wm1r, Wm2, bm2);
    else
        mma_gemm<0><<<grid, 256, SMEM_TOTAL>>>(Ah, Al, Bw, M, mode, bias, C, Cst, ldC,
                                               src, dst, gS, gT, gLd, beL, Ch, Cl,
                                               gW2, agg, ea, bm1, alpha, Wm1r, Wm2, bm2);
}

extern "C" void kernel_launch(void* const* d_in, const int* in_sizes, int n_in,
                              void* d_out, int out_size) {
    const float* pos   = (const float*)d_in[0];
    const float* ea    = (const float*)d_in[1];
    const int*   ei    = (const int*)d_in[2];
    const float* Wp    = (const float*)d_in[3];
    const float* bp    = (const float*)d_in[4];
    const float* Wa    = (const float*)d_in[5];
    const float* ba    = (const float*)d_in[6];
    const float* W1    = (const float*)d_in[7];
    const float* b1    = (const float*)d_in[8];
    const float* W2    = (const float*)d_in[9];
    const float* b2    = (const float*)d_in[10];
    const float* We    = (const float*)d_in[11];
    const float* be    = (const float*)d_in[12];
    const float* Ws    = (const float*)d_in[13];
    const float* Wt    = (const float*)d_in[14];
    const float* Wm1   = (const float*)d_in[15];
    const float* bm1   = (const float*)d_in[16];
    const float* alpha = (const float*)d_in[17];
    const float* Wm2   = (const float*)d_in[18];
    const float* bm2   = (const float*)d_in[19];
    float* out = (float*)d_out;

    const int* src = ei;
    const int* dst = ei + EE;

    cudaFuncSetAttribute(mma_gemm<1>, cudaFuncAttributeMaxDynamicSharedMemorySize, SMEM_TOTAL);
    cudaFuncSetAttribute(mma_gemm<0>, cudaFuncAttributeMaxDynamicSharedMemorySize, SMEM_TOTAL);

    float *xA, *xB, *agg, *bcat, *prec;
    fp16 *ehA, *elA, *ehB, *elB, *xh, *xl, *xcat, *Bw;
    cudaGetSymbolAddress((void**)&ehA, g_ehA);
    cudaGetSymbolAddress((void**)&elA, g_elA);
    cudaGetSymbolAddress((void**)&ehB, g_ehB);
    cudaGetSymbolAddress((void**)&elB, g_elB);
    cudaGetSymbolAddress((void**)&xA, g_xA);
    cudaGetSymbolAddress((void**)&xB, g_xB);
    cudaGetSymbolAddress((void**)&xh, g_xh);
    cudaGetSymbolAddress((void**)&xl, g_xl);
    cudaGetSymbolAddress((void**)&xcat, g_xcat);
    cudaGetSymbolAddress((void**)&agg, g_agg);
    cudaGetSymbolAddress((void**)&Bw, g_Bw);
    cudaGetSymbolAddress((void**)&bcat, g_bcat);
    cudaGetSymbolAddress((void**)&prec, g_prec);

    const int TB = 256;
    const int SLOT = UU * UU;

    int convN = 18 * 65536 + 32768 + 3072;
    convert_all_kernel<<<(convN + TB - 1) / TB, TB>>>(W1, W2, Ws, Wt, We, Wm1,
                                                      b1, b2, Bw, bcat);
    precompute_kernel<<<(3584 + TB - 1) / TB, TB>>>(Wa, ba, We, Wp, bp,
                                                    W1, W2, Ws, Wt, b1, b2, prec);
    init_x_kernel<<<(NN * 64 + TB - 1) / TB, TB>>>(pos, Wp, bp, xA);

    // --- layer 0 (rank-collapsed; no GEMMs) ---
    zero_kernel<<<(NN * 64 + TB - 1) / TB, TB>>>((float4*)agg, NN * 64);  // first-use zero
    layer0_node_kernel<<<(NN * 256 + TB - 1) / TB, TB>>>(pos, prec, xcat);
    layer0_edge_kernel<<<(EE * 64 + TB - 1) / TB, TB>>>(ea, src, dst, Wa, ba, be,
                                                        prec, xcat, ehA, elA, agg);
    node_update_kernel<<<(NN * 64 + TB - 1) / TB, TB>>>(xA, xcat, agg, xB, xh, xl);

    float* xc = xB; float* xn = xA;
    fp16 *ehc = ehA, *elc = elA, *ehn = ehB, *eln = elB;

    // --- layers 1, 2 (split=1; agg pre-zeroed by previous node_update) ---
    for (int l = 1; l < 3; l++) {
        mma_launch(1, xh, xl, Bw + (l * 5) * SLOT,
                   NN, 1024, 0, bcat + l * 1024, nullptr, xcat, 1024);
        mma_launch(1, ehc, elc, Bw + (l * 5 + 4) * SLOT,
                   EE, 256, 1, nullptr, nullptr, nullptr, 0,
                   src, dst, xcat + 512, xcat + 768, 1024,
                   be + l * 256, ehn, eln,
                   xcat + 256, agg);
        node_update_kernel<<<(NN * 64 + TB - 1) / TB, TB>>>(xc, xcat, agg, xn, xh, xl);
        { float* t = xc; xc = xn; xn = t; }
        { fp16* t = ehc; ehc = ehn; ehn = t; }
        { fp16* t = elc; elc = eln; eln = t; }
    }

    // --- final edge update (l=3): lo output dead (head reads hi only) ---
    mma_launch(1, xh, xl, Bw + 15 * SLOT,
               NN, 512, 0, nullptr, nullptr, xcat, 1024);
    mma_launch(1, ehc, elc, Bw + 17 * SLOT,
               EE, 256, 1, nullptr, nullptr, nullptr, 0,
               src, dst, xcat, xcat + 256, 1024,
               be + 3 * 256, ehn, /*Cl=*/nullptr,
               nullptr, nullptr);
    { fp16* t = ehc; ehc = ehn; ehn = t; }

    // --- fused MLP head (single col tile, hi-only A, direct store) ---
    mma_launch(0, ehc, nullptr, Bw + 18 * SLOT,
               EE, 128, 2, nullptr, out, nullptr, 0,
               nullptr, nullptr, nullptr, nullptr, 0, nullptr,
               nullptr, nullptr, nullptr, nullptr,
               ea, bm1, alpha, Wm1 + 256 * 128, Wm2, bm2);

    (void)in_sizes; (void)n_in; (void)out_size;
}